// round 10
// baseline (speedup 1.0000x reference)
#include <cuda_runtime.h>
#include <math.h>
#include <cstdint>

// Problem constants
#define Bsz   4
#define Csz   16
#define Tsz   32
#define Hsz   128
#define Wsz   128
#define Klow  4
#define TAU   0.1
#define EPS2  1e-12f          // (1e-6)^2

#define HW        (Hsz * Wsz)          // 16384
#define HW4       (HW / 4)             // 4096
#define NCOLS     (Bsz * Csz * HW4)    // 262,144 16B-columns
#define BLOCK     256
#define NBLOCKS   592                  // 4 x 148 SMs
#define NCHUNKS   (NCOLS / BLOCK)      // 1024 chunks of 256 columns
#define TPS       2                    // timesteps per stage
#define STAGES    2
#define NSTG      (Tsz / TPS)          // 16 stages per chunk
#define STAGE_TX  (2 * TPS * BLOCK * 16)   // 16384 bytes per stage (X+Y)

#define N_MAIN  ((double)Bsz * Csz * Tsz * HW)          // 33,554,432
#define N_TEMP  ((double)Bsz * Csz * (Tsz - 1) * HW)    // 32,505,856

__device__ float g_partials[2 * NBLOCKS];
__device__ unsigned int g_count = 0;   // last block resets -> graph-replay safe

__device__ __forceinline__ float sqrt_approx(float x) {
    float r;
    asm("sqrt.approx.f32 %0, %1;" : "=f"(r) : "f"(x));
    return r;
}
__device__ __forceinline__ uint32_t smaddr(const void* p) {
    return (uint32_t)__cvta_generic_to_shared(p);
}
__device__ __forceinline__ void bulk_g2s(uint32_t dst, const void* src, uint32_t mbar) {
    asm volatile(
        "cp.async.bulk.shared::cluster.global.mbarrier::complete_tx::bytes [%0], [%1], %2, [%3];"
        :: "r"(dst), "l"(src), "r"(4096u), "r"(mbar) : "memory");
}
__device__ __forceinline__ void mbar_expect_tx(uint32_t mbar, uint32_t tx) {
    asm volatile("mbarrier.arrive.expect_tx.shared.b64 _, [%0], %1;"
                 :: "r"(mbar), "r"(tx) : "memory");
}
__device__ __forceinline__ void mbar_wait(uint32_t mbar, uint32_t parity) {
    uint32_t done;
    asm volatile(
        "{\n\t.reg .pred p;\n\t"
        "mbarrier.try_wait.parity.acquire.cta.shared::cta.b64 p, [%1], %2;\n\t"
        "selp.b32 %0, 1, 0, p;\n\t}"
        : "=r"(done) : "r"(mbar), "r"(parity) : "memory");
    if (!done) {
        asm volatile(
            "{\n\t.reg .pred P1;\n\t"
            "WAIT_LOOP_%=:\n\t"
            "mbarrier.try_wait.parity.acquire.cta.shared::cta.b64 P1, [%0], %1, 0x989680;\n\t"
            "@P1 bra.uni WAIT_DONE_%=;\n\t"
            "bra.uni WAIT_LOOP_%=;\n\t"
            "WAIT_DONE_%=:\n\t}"
            :: "r"(mbar), "r"(parity) : "memory");
    }
}
// byte offset of (chunk, t=0) tile start: 256 contiguous float4 columns
__device__ __forceinline__ size_t chunk_base(int chunk) {
    unsigned col0 = (unsigned)chunk * BLOCK;
    unsigned bc   = col0 >> 12;
    unsigned hw40 = col0 & (HW4 - 1);
    return ((size_t)bc * (Tsz * HW4) + hw40) * 16;   // bytes
}

__global__ void __launch_bounds__(BLOCK)
loss_fused(const float4* __restrict__ X, const float4* __restrict__ Y,
           float* __restrict__ out)
{
    __shared__ float4 bufX[STAGES][TPS][BLOCK];   // 16 KB
    __shared__ float4 bufY[STAGES][TPS][BLOCK];   // 16 KB
    __shared__ unsigned long long mbar[STAGES];
    __shared__ float  sD[Klow][Tsz];
    __shared__ float4 sWT[Tsz];
    __shared__ float  sG[Klow * Klow];
    __shared__ float  red[2][BLOCK];
    __shared__ bool   is_last;

    const int tid = threadIdx.x;

    // DCT tables
    if (tid < Tsz) {
        const float s  = sqrtf(2.0f / (float)Tsz);
        const float ph = (float)M_PI * (2.0f * tid + 1.0f) / (2.0f * (float)Tsz);
        float w0 = s * 0.7071067811865476f;
        float w1 = s * cosf(ph);
        float w2 = s * cosf(2.0f * ph);
        float w3 = s * cosf(3.0f * ph);
        sD[0][tid] = w0; sD[1][tid] = w1; sD[2][tid] = w2; sD[3][tid] = w3;
        sWT[tid] = make_float4(w0, w1, w2, w3);
    }
    if (tid == BLOCK - 1) {
        #pragma unroll
        for (int s = 0; s < STAGES; s++)
            asm volatile("mbarrier.init.shared.b64 [%0], %1;"
                         :: "r"(smaddr(&mbar[s])), "r"(1u) : "memory");
    }
    __syncthreads();
    if (tid < Klow * Klow) {
        int n = tid >> 2, m = tid & 3;
        float g = 0.0f;
        #pragma unroll
        for (int s = 0; s < Tsz - 1; s++)
            g += (sD[n][s + 1] - sD[n][s]) * (sD[m][s + 1] - sD[m][s]);
        sG[tid] = g;
    }
    __syncthreads();

    const int c0   = blockIdx.x;
    const int c1   = blockIdx.x + NBLOCKS;
    const int total = (c1 < NCHUNKS) ? 2 * NSTG : NSTG;
    const char* xb = (const char*)X;
    const char* yb = (const char*)Y;

    // Issue stage gs2 (producer: one thread)
    #define ISSUE(gs2) do {                                                   \
        int ch_ = ((gs2) >= NSTG) ? c1 : c0;                                  \
        int ts_ = (gs2) & (NSTG - 1);                                         \
        int st_ = (gs2) & 1;                                                  \
        size_t b_ = chunk_base(ch_);                                          \
        uint32_t mb_ = smaddr(&mbar[st_]);                                    \
        mbar_expect_tx(mb_, STAGE_TX);                                        \
        _Pragma("unroll")                                                     \
        for (int j_ = 0; j_ < TPS; j_++) {                                    \
            size_t off_ = b_ + (size_t)(ts_ * TPS + j_) * (HW4 * 16);         \
            bulk_g2s(smaddr(&bufX[st_][j_][0]), xb + off_, mb_);              \
            bulk_g2s(smaddr(&bufY[st_][j_][0]), yb + off_, mb_);              \
        }                                                                     \
    } while (0)

    if (tid == 0) { ISSUE(0); ISSUE(1); }

    int ph0 = 0, ph1 = 0;
    float ch0 = 0.f, ch1 = 0.f, ch2 = 0.f, ch3 = 0.f;
    float temp = 0.0f;
    float c[Klow][4];
    #pragma unroll
    for (int n = 0; n < Klow; n++)
        #pragma unroll
        for (int l = 0; l < 4; l++) c[n][l] = 0.0f;

    #pragma unroll 1
    for (int gs = 0; gs < total; gs++) {
        const int s  = gs & 1;
        const int ts = gs & (NSTG - 1);
        mbar_wait(smaddr(&mbar[s]), s ? ph1 : ph0);
        if (s) ph1 ^= 1; else ph0 ^= 1;

        #pragma unroll
        for (int j = 0; j < TPS; j++) {
            float4 a = bufX[s][j][tid];
            float4 b = bufY[s][j][tid];
            float d0 = a.x - b.x, d1 = a.y - b.y, d2 = a.z - b.z, d3 = a.w - b.w;

            ch0 += sqrt_approx(fmaf(d0, d0, EPS2));
            ch1 += sqrt_approx(fmaf(d1, d1, EPS2));
            ch2 += sqrt_approx(fmaf(d2, d2, EPS2));
            ch3 += sqrt_approx(fmaf(d3, d3, EPS2));

            const float4 w = sWT[ts * TPS + j];
            c[0][0] = fmaf(d0, w.x, c[0][0]);
            c[0][1] = fmaf(d1, w.x, c[0][1]);
            c[0][2] = fmaf(d2, w.x, c[0][2]);
            c[0][3] = fmaf(d3, w.x, c[0][3]);
            c[1][0] = fmaf(d0, w.y, c[1][0]);
            c[1][1] = fmaf(d1, w.y, c[1][1]);
            c[1][2] = fmaf(d2, w.y, c[1][2]);
            c[1][3] = fmaf(d3, w.y, c[1][3]);
            c[2][0] = fmaf(d0, w.z, c[2][0]);
            c[2][1] = fmaf(d1, w.z, c[2][1]);
            c[2][2] = fmaf(d2, w.z, c[2][2]);
            c[2][3] = fmaf(d3, w.z, c[2][3]);
            c[3][0] = fmaf(d0, w.w, c[3][0]);
            c[3][1] = fmaf(d1, w.w, c[3][1]);
            c[3][2] = fmaf(d2, w.w, c[3][2]);
            c[3][3] = fmaf(d3, w.w, c[3][3]);
        }
        __syncthreads();                       // everyone done reading buffer s
        if (tid == 0 && gs + STAGES < total) ISSUE(gs + STAGES);

        if (ts == NSTG - 1) {                  // chunk finished: fold c^T G c
            #pragma unroll
            for (int l = 0; l < 4; l++) {
                #pragma unroll
                for (int n = 0; n < Klow; n++) {
                    float acc = 0.0f;
                    #pragma unroll
                    for (int m = 0; m < Klow; m++)
                        acc = fmaf(c[m][l], sG[n * Klow + m], acc);
                    temp = fmaf(c[n][l], acc, temp);
                }
            }
            #pragma unroll
            for (int n = 0; n < Klow; n++)
                #pragma unroll
                for (int l = 0; l < 4; l++) c[n][l] = 0.0f;
        }
    }
    float charb = (ch0 + ch1) + (ch2 + ch3);

    // Deterministic block reduction
    red[0][tid] = charb;
    red[1][tid] = temp;
    __syncthreads();
    for (int s = BLOCK / 2; s > 0; s >>= 1) {
        if (tid < s) {
            red[0][tid] += red[0][tid + s];
            red[1][tid] += red[1][tid + s];
        }
        __syncthreads();
    }

    if (tid == 0) {
        g_partials[blockIdx.x]           = red[0][0];
        g_partials[NBLOCKS + blockIdx.x] = red[1][0];
        __threadfence();
        unsigned int ticket = atomicAdd(&g_count, 1u);
        is_last = (ticket == NBLOCKS - 1);
    }
    __syncthreads();

    if (is_last) {
        __shared__ double r0[BLOCK];
        __shared__ double r1[BLOCK];
        double s0 = 0.0, s1 = 0.0;
        #pragma unroll 3
        for (int k = tid; k < NBLOCKS; k += BLOCK) {
            s0 += (double)__ldcg(&g_partials[k]);
            s1 += (double)__ldcg(&g_partials[NBLOCKS + k]);
        }
        r0[tid] = s0;
        r1[tid] = s1;
        __syncthreads();
        for (int s = BLOCK / 2; s > 0; s >>= 1) {
            if (tid < s) {
                r0[tid] += r0[tid + s];
                r1[tid] += r1[tid + s];
            }
            __syncthreads();
        }
        if (tid == 0) {
            double L_main = r0[0] / N_MAIN;
            double L_temp = r1[0] / N_TEMP;
            double total_ = L_main + TAU * L_temp;
            out[0] = (float)total_;
            out[1] = (float)L_main;
            out[2] = (float)L_temp;
            g_count = 0;   // reset for next graph replay
        }
    }
}

extern "C" void kernel_launch(void* const* d_in, const int* in_sizes, int n_in,
                              void* d_out, int out_size)
{
    const float4* X = (const float4*)d_in[0];
    const float4* Y = (const float4*)d_in[1];
    float* out = (float*)d_out;

    loss_fused<<<NBLOCKS, BLOCK>>>(X, Y, out);
}

// round 11
// speedup vs baseline: 1.0421x; 1.0421x over previous
#include <cuda_runtime.h>
#include <math.h>

// Problem constants
#define Bsz   4
#define Csz   16
#define Tsz   32
#define Hsz   128
#define Wsz   128
#define Klow  4
#define TAU   0.1
#define EPS2  1e-12f          // (1e-6)^2

#define HW        (Hsz * Wsz)          // 16384
#define HW4       (HW / 4)             // 4096
#define NCOLS     (Bsz * Csz * HW4)    // 262,144 16B-columns
#define BLOCK     256
#define NBLOCKS   512                  // all co-resident -> zero wave tail (R8 best)
#define NTHREADS  (NBLOCKS * BLOCK)    // 131,072 -> 2 columns per thread
#define COLS_PER_THREAD 2

#define N_MAIN  ((double)Bsz * Csz * Tsz * HW)          // 33,554,432
#define N_TEMP  ((double)Bsz * Csz * (Tsz - 1) * HW)    // 32,505,856

// ---------- compile-time DCT tables -> FFMA immediates ----------
// All generators are __host__ __device__ constexpr so the constant-expression
// evaluation is legal in device code WITHOUT --expt-relaxed-constexpr
// (R3 failed because the table was a host-only namespace symbol).
__host__ __device__ constexpr double c_reduce(double x) {
    while (x >  3.14159265358979323846) x -= 6.28318530717958647692;
    while (x < -3.14159265358979323846) x += 6.28318530717958647692;
    return x;
}
__host__ __device__ constexpr double c_cos(double x) {
    x = c_reduce(x);
    double x2 = x * x, term = 1.0, sum = 1.0;
    for (int i = 1; i <= 13; i++) {
        term *= -x2 / (double)((2 * i - 1) * (2 * i));
        sum  += term;
    }
    return sum;
}
__host__ __device__ constexpr double c_sqrt(double v) {
    double r = v > 1.0 ? v : 1.0;
    for (int i = 0; i < 64; i++) r = 0.5 * (r + v / r);
    return r;
}
struct Tab {
    float D[Klow][Tsz];
    float G[Klow][Klow];
};
__host__ __device__ constexpr Tab make_tab() {
    Tab r{};
    double Dd[Klow][Tsz] = {};
    const double scale = c_sqrt(2.0 / (double)Tsz);
    for (int n = 0; n < Klow; n++)
        for (int t = 0; t < Tsz; t++) {
            double v = scale * c_cos(3.14159265358979323846 * (2.0 * t + 1.0) * n / (2.0 * Tsz));
            if (n == 0) v *= 0.70710678118654752440;
            Dd[n][t] = v;
            r.D[n][t] = (float)v;
        }
    for (int n = 0; n < Klow; n++)
        for (int m = 0; m < Klow; m++) {
            double g = 0.0;
            for (int s = 0; s < Tsz - 1; s++)
                g += (Dd[n][s + 1] - Dd[n][s]) * (Dd[m][s + 1] - Dd[m][s]);
            r.G[n][m] = (float)g;
        }
    return r;
}

// ---------- global scratch ----------
__device__ float g_partials[2 * NBLOCKS];
__device__ unsigned int g_count = 0;   // last block resets -> graph-replay safe

// Single-MUFU sqrt (harness has no -use_fast_math; sqrtf would emit a ~15-instr
// correctly-rounded emulation sequence).
__device__ __forceinline__ float sqrt_approx(float x) {
    float r;
    asm("sqrt.approx.f32 %0, %1;" : "=f"(r) : "f"(x));
    return r;
}

__global__ void __launch_bounds__(BLOCK)
loss_fused(const float4* __restrict__ X, const float4* __restrict__ Y,
           float* __restrict__ out)
{
    constexpr Tab TAB = make_tab();   // compile-time; indices below are unroll-constant

    __shared__ float red[2][BLOCK];
    __shared__ bool  is_last;

    const int tid = threadIdx.x;

    // Thread handles columns i and i + NTHREADS (same hw4, bc offset +32).
    const unsigned i   = blockIdx.x * BLOCK + tid;
    const unsigned hw4 = i & (HW4 - 1);
    const unsigned bc  = i >> 12;               // 0..31; second col is bc+32
    const size_t base0 = (size_t)bc * (Tsz * HW4) + hw4;

    float ch0 = 0.f, ch1 = 0.f, ch2 = 0.f, ch3 = 0.f;
    float temp = 0.0f;

    // CRITICAL: unroll 1 — merging both columns' 128 loads into one straight
    // line makes ptxas spill (R6: +229 MB DRAM traffic).
    #pragma unroll 1
    for (int colit = 0; colit < COLS_PER_THREAD; colit++) {
        const size_t base = base0 + (size_t)colit * 32 * (Tsz * HW4);
        const float4* __restrict__ px = X + base;
        const float4* __restrict__ py = Y + base;

        float c[Klow][4];               // [dct row][lane]
        #pragma unroll
        for (int n = 0; n < Klow; n++)
            #pragma unroll
            for (int l = 0; l < 4; l++) c[n][l] = 0.0f;

        // 4-timestep staging: 8 independent LDG.128 issued before any use.
        #pragma unroll
        for (int tt = 0; tt < Tsz; tt += 4) {
            float4 a[4], b[4];
            #pragma unroll
            for (int j = 0; j < 4; j++) {
                a[j] = __ldcs(&px[(tt + j) * HW4]);
                b[j] = __ldcs(&py[(tt + j) * HW4]);
            }
            #pragma unroll
            for (int j = 0; j < 4; j++) {
                float d0 = a[j].x - b[j].x;
                float d1 = a[j].y - b[j].y;
                float d2 = a[j].z - b[j].z;
                float d3 = a[j].w - b[j].w;

                ch0 += sqrt_approx(fmaf(d0, d0, EPS2));
                ch1 += sqrt_approx(fmaf(d1, d1, EPS2));
                ch2 += sqrt_approx(fmaf(d2, d2, EPS2));
                ch3 += sqrt_approx(fmaf(d3, d3, EPS2));

                // Weights fold to FFMA immediates (t = tt+j is unroll-constant)
                #pragma unroll
                for (int n = 0; n < Klow; n++) {
                    const float w = TAB.D[n][tt + j];
                    c[n][0] = fmaf(d0, w, c[n][0]);
                    c[n][1] = fmaf(d1, w, c[n][1]);
                    c[n][2] = fmaf(d2, w, c[n][2]);
                    c[n][3] = fmaf(d3, w, c[n][3]);
                }
            }
        }

        // temp += sum over 4 lanes of c^T G c  (G as immediates)
        #pragma unroll
        for (int l = 0; l < 4; l++) {
            #pragma unroll
            for (int n = 0; n < Klow; n++) {
                float acc = 0.0f;
                #pragma unroll
                for (int m = 0; m < Klow; m++)
                    acc = fmaf(c[m][l], TAB.G[n][m], acc);
                temp = fmaf(c[n][l], acc, temp);
            }
        }
    }
    float charb = (ch0 + ch1) + (ch2 + ch3);

    // Deterministic block reduction
    red[0][tid] = charb;
    red[1][tid] = temp;
    __syncthreads();
    for (int s = BLOCK / 2; s > 0; s >>= 1) {
        if (tid < s) {
            red[0][tid] += red[0][tid + s];
            red[1][tid] += red[1][tid + s];
        }
        __syncthreads();
    }

    if (tid == 0) {
        g_partials[blockIdx.x]           = red[0][0];
        g_partials[NBLOCKS + blockIdx.x] = red[1][0];
        __threadfence();
        unsigned int ticket = atomicAdd(&g_count, 1u);
        is_last = (ticket == NBLOCKS - 1);
    }
    __syncthreads();

    // Last block: deterministic final reduction in double
    if (is_last) {
        __shared__ double r0[BLOCK];
        __shared__ double r1[BLOCK];
        double s0 = 0.0, s1 = 0.0;
        #pragma unroll 2
        for (int k = tid; k < NBLOCKS; k += BLOCK) {
            s0 += (double)__ldcg(&g_partials[k]);
            s1 += (double)__ldcg(&g_partials[NBLOCKS + k]);
        }
        r0[tid] = s0;
        r1[tid] = s1;
        __syncthreads();
        for (int s = BLOCK / 2; s > 0; s >>= 1) {
            if (tid < s) {
                r0[tid] += r0[tid + s];
                r1[tid] += r1[tid + s];
            }
            __syncthreads();
        }
        if (tid == 0) {
            double L_main = r0[0] / N_MAIN;
            double L_temp = r1[0] / N_TEMP;
            double total  = L_main + TAU * L_temp;
            out[0] = (float)total;
            out[1] = (float)L_main;
            out[2] = (float)L_temp;
            g_count = 0;   // reset for next graph replay
        }
    }
}

extern "C" void kernel_launch(void* const* d_in, const int* in_sizes, int n_in,
                              void* d_out, int out_size)
{
    const float4* X = (const float4*)d_in[0];
    const float4* Y = (const float4*)d_in[1];
    float* out = (float*)d_out;

    loss_fused<<<NBLOCKS, BLOCK>>>(X, Y, out);
}